// round 2
// baseline (speedup 1.0000x reference)
#include <cuda_runtime.h>
#include <cstdint>

#define Nn 2048
#define Bb 64
#define Tt 128
#define Ii 4
#define NSENS 256
#define NOUT 128
#define Oo 2
#define KMICRO 4
#define NBLK 128
#define NT 16        // neurons per block
#define NTHREADS 256
#define KC 128       // k-chunk staged in smem

// persistent state (scratch): h double buffer in [neuron][batch] layout
__device__ float g_h[2][Nn * Bb];
__device__ unsigned g_count;
__device__ volatile unsigned g_gen;

__global__ void hx_init_kernel() {
    int i = blockIdx.x * blockDim.x + threadIdx.x;
    if (i == 0) { g_count = 0u; g_gen = 0u; }
    int stride = gridDim.x * blockDim.x;
    for (int j = i; j < Nn * Bb; j += stride) {
        g_h[0][j] = 0.0f;
        g_h[1][j] = 0.0f;
    }
}

__device__ __forceinline__ void grid_barrier(unsigned step) {
    __syncthreads();
    if (threadIdx.x == 0) {
        unsigned a = atomicAdd(&g_count, 1u);
        if (a == (unsigned)(gridDim.x - 1)) {
            g_count = 0u;
            __threadfence();
            g_gen = step;
        } else {
            while (g_gen < step) { }
            __threadfence();
        }
    }
    __syncthreads();
}

__global__ void __launch_bounds__(NTHREADS, 1) hx_rnn_kernel(
    const float* __restrict__ inputs,   // [B, T, I]
    const float* __restrict__ W,        // [N, N]  (W_rec; out[b,n]=sum_k h[b,k]*W[n,k])
    const float* __restrict__ W_in,     // [NSENS, I]
    const float* __restrict__ b_in,     // [NSENS]
    const float* __restrict__ W_out,    // [O, NOUT]
    const float* __restrict__ b_out,    // [O]
    const void*  sens_idx_p,            // [NSENS] int32 or int64
    const void*  out_idx_p,             // [NOUT] int32 or int64
    float* __restrict__ out)            // [B, T, O]
{
    __shared__ float sh[KC * Bb];       // 32KB h chunk: sh[k][b]
    __shared__ int s_map[NT];           // neuron -> sensory slot (or -1)
    __shared__ int s_out_idx[NOUT];
    __shared__ float s_wout[Oo * NOUT];
    __shared__ int s_flags;

    const int tid = threadIdx.x;
    const int blk = blockIdx.x;
    const int n0 = blk * NT;

    // ---- dtype detection for index arrays (int64 vs int32) ----
    if (tid == 0) {
        const int* ws = (const int*)sens_idx_p;
        int s64 = 1;
        for (int i = 1; i < NSENS; i += 2) { if (ws[i] != 0) { s64 = 0; break; } }
        const int* wo = (const int*)out_idx_p;
        int o64 = 1;
        for (int i = 1; i < NOUT; i += 2) { if (wo[i] != 0) { o64 = 0; break; } }
        s_flags = s64 | (o64 << 1);
    }
    if (tid < NT) s_map[tid] = -1;
    __syncthreads();
    const bool s64 = (s_flags & 1) != 0;
    const bool o64 = (s_flags & 2) != 0;

    // ---- build per-block sensory map ----
    for (int s = tid; s < NSENS; s += NTHREADS) {
        int idx = s64 ? (int)((const long long*)sens_idx_p)[s]
                      : ((const int*)sens_idx_p)[s];
        if (idx >= n0 && idx < n0 + NT) s_map[idx - n0] = s;
    }
    if (blk == 0) {
        for (int j = tid; j < NOUT; j += NTHREADS)
            s_out_idx[j] = o64 ? (int)((const long long*)out_idx_p)[j]
                               : ((const int*)out_idx_p)[j];
        for (int j = tid; j < Oo * NOUT; j += NTHREADS) s_wout[j] = W_out[j];
    }
    __syncthreads();

    // ---- thread -> (neuron, batch quad) mapping ----
    // warp covers 8 neurons x 16 batches => low smem crossbar pressure
    const int w  = tid >> 5;
    const int l  = tid & 31;
    const int gn = w & 1;          // 2 neuron groups of 8
    const int gb = w >> 1;         // 4 batch groups of 16
    const int nin   = l >> 2;      // 0..7
    const int bgin  = l & 3;       // 0..3
    const int nloc  = gn * 8 + nin;          // 0..15
    const int n     = n0 + nloc;
    const int bbase = gb * 16 + bgin * 4;    // 4 consecutive batches
    const float* Wrow = W + (size_t)n * Nn;

    const unsigned sbase = (unsigned)__cvta_generic_to_shared(sh);
    const int s_slot = s_map[nloc];
    const float* wi = (s_slot >= 0) ? (W_in + s_slot * Ii) : W_in;
    const float bi  = (s_slot >= 0) ? b_in[s_slot] : 0.0f;

    unsigned step = 1;
    int p = 0;

    for (int t = 0; t < Tt; ++t) {
        for (int mi = 0; mi < KMICRO; ++mi) {
            const float* cur = g_h[p];
            float* nxt = g_h[p ^ 1];

            unsigned long long a01 = 0ull, a23 = 0ull;  // f32x2 accumulators (=0.f,0.f)

            for (int kc = 0; kc < Nn; kc += KC) {
                __syncthreads();
                // stage h chunk [KC][Bb] -> smem (L2-coherent loads)
                const float4* src = (const float4*)(cur + kc * Bb);
                float4* dst4 = (float4*)sh;
                #pragma unroll
                for (int i = 0; i < (KC * Bb / 4) / NTHREADS; ++i)
                    dst4[tid + i * NTHREADS] = __ldcg(src + tid + i * NTHREADS);
                __syncthreads();

                const float* wrow_kc = Wrow + kc;
                #pragma unroll 4
                for (int kk = 0; kk < KC; kk += 4) {
                    float4 wv = __ldg((const float4*)(wrow_kc + kk));
                    #pragma unroll
                    for (int j = 0; j < 4; ++j) {
                        float wj = (j == 0) ? wv.x : (j == 1) ? wv.y
                                 : (j == 2) ? wv.z : wv.w;
                        unsigned addr = sbase + (unsigned)((((kk + j) * Bb) + bbase) * 4);
                        unsigned long long h01, h23, wp;
                        asm volatile("ld.shared.v2.b64 {%0, %1}, [%2];"
                                     : "=l"(h01), "=l"(h23) : "r"(addr));
                        asm("mov.b64 %0, {%1, %2};" : "=l"(wp) : "f"(wj), "f"(wj));
                        asm("fma.rn.f32x2 %0, %1, %2, %3;"
                            : "=l"(a01) : "l"(h01), "l"(wp), "l"(a01));
                        asm("fma.rn.f32x2 %0, %1, %2, %3;"
                            : "=l"(a23) : "l"(h23), "l"(wp), "l"(a23));
                    }
                }
            }

            float v0, v1, v2, v3;
            asm("mov.b64 {%0, %1}, %2;" : "=f"(v0), "=f"(v1) : "l"(a01));
            asm("mov.b64 {%0, %1}, %2;" : "=f"(v2), "=f"(v3) : "l"(a23));

            if (mi == 0 && s_slot >= 0) {
                // injection = x_t @ W_in^T + b_in at this sensory neuron
                const float w0 = wi[0], w1 = wi[1], w2 = wi[2], w3 = wi[3];
                const float* x0 = inputs + (size_t)(bbase + 0) * (Tt * Ii) + t * Ii;
                const float* x1 = inputs + (size_t)(bbase + 1) * (Tt * Ii) + t * Ii;
                const float* x2 = inputs + (size_t)(bbase + 2) * (Tt * Ii) + t * Ii;
                const float* x3 = inputs + (size_t)(bbase + 3) * (Tt * Ii) + t * Ii;
                v0 += bi + x0[0]*w0 + x0[1]*w1 + x0[2]*w2 + x0[3]*w3;
                v1 += bi + x1[0]*w0 + x1[1]*w1 + x1[2]*w2 + x1[3]*w3;
                v2 += bi + x2[0]*w0 + x2[1]*w1 + x2[2]*w2 + x2[3]*w3;
                v3 += bi + x3[0]*w0 + x3[1]*w1 + x3[2]*w2 + x3[3]*w3;
            }

            float4 ov = make_float4(fmaxf(v0, 0.0f), fmaxf(v1, 0.0f),
                                    fmaxf(v2, 0.0f), fmaxf(v3, 0.0f));
            __stcg((float4*)(nxt + n * Bb + bbase), ov);

            __threadfence();           // release h writes to L2
            grid_barrier(step++);      // global sync
            p ^= 1;
        }

        // ---- readout for timestep t (block 0 only; races argued safe:
        // g_h[p] is not overwritten until after the next barrier, which
        // requires block 0's arrival, which happens after this finishes) ----
        if (blk == 0 && tid < Oo * Bb) {
            const float* hf = g_h[p];
            int o = tid >> 6;
            int b = tid & 63;
            float acc = b_out[o];
            const float* wrow = s_wout + o * NOUT;
            #pragma unroll 4
            for (int j = 0; j < NOUT; ++j)
                acc += wrow[j] * __ldcg(hf + (size_t)s_out_idx[j] * Bb + b);
            out[(size_t)b * (Tt * Oo) + t * Oo + o] = acc;
        }
    }
}

extern "C" void kernel_launch(void* const* d_in, const int* in_sizes, int n_in,
                              void* d_out, int out_size) {
    (void)in_sizes; (void)n_in; (void)out_size;
    const float* inputs = (const float*)d_in[0];
    const float* W_rec  = (const float*)d_in[1];
    const float* W_in   = (const float*)d_in[2];
    const float* b_in   = (const float*)d_in[3];
    const float* W_out  = (const float*)d_in[4];
    const float* b_out  = (const float*)d_in[5];
    const void*  s_idx  = d_in[6];
    const void*  o_idx  = d_in[7];

    hx_init_kernel<<<128, 256>>>();
    hx_rnn_kernel<<<NBLK, NTHREADS>>>(inputs, W_rec, W_in, b_in, W_out, b_out,
                                      s_idx, o_idx, (float*)d_out);
}

// round 3
// speedup vs baseline: 2.7687x; 2.7687x over previous
#include <cuda_runtime.h>
#include <cstdint>

#define Nn 2048
#define Bb 64
#define Tt 128
#define Ii 4
#define NSENS 256
#define NOUT 128
#define Oo 2
#define KMICRO 4
#define NBLK 128
#define NT 16            // neurons per block
#define NTHREADS 256
#define NWARP 8
#define KSLICE (Nn / NWARP)     // 256 k per warp (split-K)
#define NGROUP (KSLICE / 4)     // 64 groups of 4 k
#define SMEM_DYN ((Nn * NT + NWARP * NT * Bb) * 4)   // 128KB W + 32KB partials

// persistent state: h double buffer, layout [neuron][batch]
__device__ __align__(128) float g_h[2][Nn * Bb];
__device__ unsigned g_count;
__device__ volatile unsigned g_gen;

__global__ void hx_init_kernel() {
    int i = blockIdx.x * blockDim.x + threadIdx.x;
    if (i == 0) { g_count = 0u; g_gen = 0u; }
    int stride = gridDim.x * blockDim.x;
    for (int j = i; j < Nn * Bb; j += stride) {
        g_h[0][j] = 0.0f;
        g_h[1][j] = 0.0f;
    }
}

__device__ __forceinline__ void grid_barrier(unsigned step) {
    __syncthreads();
    if (threadIdx.x == 0) {
        unsigned a = atomicAdd(&g_count, 1u);
        if (a == (unsigned)(gridDim.x - 1)) {
            g_count = 0u;
            __threadfence();
            g_gen = step;
        } else {
            while (g_gen < step) { }
            __threadfence();
        }
    }
    __syncthreads();
}

// load one 4-k group of h: 16 f32x2 pairs (4 k x 8 batches), L2-coherent
__device__ __forceinline__ void load_hgroup(unsigned long long* hv, const float* base) {
    #pragma unroll
    for (int j = 0; j < 4; ++j) {
        asm volatile("ld.global.cg.v2.u64 {%0,%1}, [%2];"
                     : "=l"(hv[j * 4 + 0]), "=l"(hv[j * 4 + 1])
                     : "l"(base + j * Bb));
        asm volatile("ld.global.cg.v2.u64 {%0,%1}, [%2];"
                     : "=l"(hv[j * 4 + 2]), "=l"(hv[j * 4 + 3])
                     : "l"(base + j * Bb + 4));
    }
}

// 4 k-steps: per k, 1 LDS.128 of W (4 neurons) -> 16 FFMA2
__device__ __forceinline__ void compute_group(unsigned long long* acc,
                                              const unsigned long long* hv,
                                              const float* swp) {
    #pragma unroll
    for (int j = 0; j < 4; ++j) {
        float4 wv = *(const float4*)(swp + j * NT);
        unsigned long long wp0, wp1, wp2, wp3;
        asm("mov.b64 %0, {%1, %1};" : "=l"(wp0) : "f"(wv.x));
        asm("mov.b64 %0, {%1, %1};" : "=l"(wp1) : "f"(wv.y));
        asm("mov.b64 %0, {%1, %1};" : "=l"(wp2) : "f"(wv.z));
        asm("mov.b64 %0, {%1, %1};" : "=l"(wp3) : "f"(wv.w));
        #pragma unroll
        for (int bp = 0; bp < 4; ++bp) {
            asm("fma.rn.f32x2 %0, %1, %2, %3;"
                : "=l"(acc[0 * 4 + bp]) : "l"(hv[j * 4 + bp]), "l"(wp0), "l"(acc[0 * 4 + bp]));
            asm("fma.rn.f32x2 %0, %1, %2, %3;"
                : "=l"(acc[1 * 4 + bp]) : "l"(hv[j * 4 + bp]), "l"(wp1), "l"(acc[1 * 4 + bp]));
            asm("fma.rn.f32x2 %0, %1, %2, %3;"
                : "=l"(acc[2 * 4 + bp]) : "l"(hv[j * 4 + bp]), "l"(wp2), "l"(acc[2 * 4 + bp]));
            asm("fma.rn.f32x2 %0, %1, %2, %3;"
                : "=l"(acc[3 * 4 + bp]) : "l"(hv[j * 4 + bp]), "l"(wp3), "l"(acc[3 * 4 + bp]));
        }
    }
}

__global__ void __launch_bounds__(NTHREADS, 1) hx_rnn_kernel(
    const float* __restrict__ inputs,   // [B, T, I]
    const float* __restrict__ W,        // [N, N]
    const float* __restrict__ W_in,     // [NSENS, I]
    const float* __restrict__ b_in,     // [NSENS]
    const float* __restrict__ W_out,    // [O, NOUT]
    const float* __restrict__ b_out,    // [O]
    const void*  sens_idx_p,
    const void*  out_idx_p,
    float* __restrict__ out)            // [B, T, O]
{
    extern __shared__ float smem[];
    float* sw    = smem;                 // [2048][16] W tile, transposed, resident
    float* spart = smem + Nn * NT;       // [8][16][64] split-K partials

    __shared__ int s_map[NT];
    __shared__ int s_out_idx[NOUT];
    __shared__ float s_wout[Oo * NOUT];
    __shared__ int s_flags;

    const int tid = threadIdx.x;
    const int blk = blockIdx.x;
    const int n0 = blk * NT;

    // ---- index dtype detection (int64 vs int32) ----
    if (tid == 0) {
        const int* ws = (const int*)sens_idx_p;
        int s64 = 1;
        for (int i = 1; i < NSENS; i += 2) { if (ws[i] != 0) { s64 = 0; break; } }
        const int* wo = (const int*)out_idx_p;
        int o64 = 1;
        for (int i = 1; i < NOUT; i += 2) { if (wo[i] != 0) { o64 = 0; break; } }
        s_flags = s64 | (o64 << 1);
    }
    if (tid < NT) s_map[tid] = -1;
    __syncthreads();
    const bool s64 = (s_flags & 1) != 0;
    const bool o64 = (s_flags & 2) != 0;

    for (int s = tid; s < NSENS; s += NTHREADS) {
        int idx = s64 ? (int)((const long long*)sens_idx_p)[s]
                      : ((const int*)sens_idx_p)[s];
        if (idx >= n0 && idx < n0 + NT) s_map[idx - n0] = s;
    }
    for (int j = tid; j < NOUT; j += NTHREADS)
        s_out_idx[j] = o64 ? (int)((const long long*)out_idx_p)[j]
                           : ((const int*)out_idx_p)[j];
    for (int j = tid; j < Oo * NOUT; j += NTHREADS) s_wout[j] = W_out[j];

    // ---- stage W tile (16 rows) transposed into smem: sw[k][n] ----
    for (int idx = tid; idx < NT * Nn; idx += NTHREADS) {
        int n = idx >> 11;          // / 2048
        int k = idx & (Nn - 1);
        sw[k * NT + n] = W[(size_t)(n0 + n) * Nn + k];
    }
    __syncthreads();

    // ---- thread mapping: warp = k-slice; lane = (4 neurons) x (8 batches) ----
    const int w  = tid >> 5;
    const int l  = tid & 31;
    const int bl = l & 7;               // batches bl*8 .. bl*8+7
    const int nl = l >> 3;              // neurons nl*4 .. nl*4+3
    const int kbase = w * KSLICE;
    const float* swbase = sw + kbase * NT + nl * 4;

    // reduction-phase mapping
    const int rn = tid >> 4;            // 0..15 local neuron
    const int rq = tid & 15;            // batch quad
    const int r_slot = s_map[rn];
    const float* r_wi = (r_slot >= 0) ? (W_in + r_slot * Ii) : W_in;
    const float r_bi  = (r_slot >= 0) ? b_in[r_slot] : 0.0f;

    unsigned step = 1;
    int p = 0;

    for (int t = 0; t < Tt; ++t) {
        for (int mi = 0; mi < KMICRO; ++mi) {
            const float* cur = g_h[p];
            float* nxt = g_h[p ^ 1];

            unsigned long long acc[16];
            #pragma unroll
            for (int i = 0; i < 16; ++i) acc[i] = 0ull;

            const float* hbase = cur + kbase * Bb + bl * 8;
            unsigned long long A[16], Bv[16];

            load_hgroup(A, hbase);
            #pragma unroll 1
            for (int gi = 0; gi < NGROUP - 2; gi += 2) {
                load_hgroup(Bv, hbase + (gi + 1) * 4 * Bb);
                compute_group(acc, A, swbase + gi * 4 * NT);
                load_hgroup(A, hbase + (gi + 2) * 4 * Bb);
                compute_group(acc, Bv, swbase + (gi + 1) * 4 * NT);
            }
            load_hgroup(Bv, hbase + (NGROUP - 1) * 4 * Bb);
            compute_group(acc, A, swbase + (NGROUP - 2) * 4 * NT);
            compute_group(acc, Bv, swbase + (NGROUP - 1) * 4 * NT);

            // ---- write split-K partials ----
            {
                float* pp = spart + (w * NT + nl * 4) * Bb + bl * 8;
                #pragma unroll
                for (int i = 0; i < 4; ++i) {
                    float f0, f1, f2, f3, f4, f5, f6, f7;
                    asm("mov.b64 {%0,%1}, %2;" : "=f"(f0), "=f"(f1) : "l"(acc[i * 4 + 0]));
                    asm("mov.b64 {%0,%1}, %2;" : "=f"(f2), "=f"(f3) : "l"(acc[i * 4 + 1]));
                    asm("mov.b64 {%0,%1}, %2;" : "=f"(f4), "=f"(f5) : "l"(acc[i * 4 + 2]));
                    asm("mov.b64 {%0,%1}, %2;" : "=f"(f6), "=f"(f7) : "l"(acc[i * 4 + 3]));
                    *(float4*)(pp + i * Bb)     = make_float4(f0, f1, f2, f3);
                    *(float4*)(pp + i * Bb + 4) = make_float4(f4, f5, f6, f7);
                }
            }
            __syncthreads();

            // ---- reduce 8 partials, inject, relu, store ----
            {
                const float* rp = spart + rn * Bb + rq * 4;
                float4 s = *(const float4*)rp;
                #pragma unroll
                for (int ww = 1; ww < NWARP; ++ww) {
                    float4 q = *(const float4*)(rp + ww * NT * Bb);
                    s.x += q.x; s.y += q.y; s.z += q.z; s.w += q.w;
                }
                if (mi == 0 && r_slot >= 0) {
                    const float w0 = r_wi[0], w1 = r_wi[1], w2 = r_wi[2], w3 = r_wi[3];
                    const int b0 = rq * 4;
                    const float* x0 = inputs + (size_t)(b0 + 0) * (Tt * Ii) + t * Ii;
                    const float* x1 = inputs + (size_t)(b0 + 1) * (Tt * Ii) + t * Ii;
                    const float* x2 = inputs + (size_t)(b0 + 2) * (Tt * Ii) + t * Ii;
                    const float* x3 = inputs + (size_t)(b0 + 3) * (Tt * Ii) + t * Ii;
                    s.x += r_bi + x0[0]*w0 + x0[1]*w1 + x0[2]*w2 + x0[3]*w3;
                    s.y += r_bi + x1[0]*w0 + x1[1]*w1 + x1[2]*w2 + x1[3]*w3;
                    s.z += r_bi + x2[0]*w0 + x2[1]*w1 + x2[2]*w2 + x2[3]*w3;
                    s.w += r_bi + x3[0]*w0 + x3[1]*w1 + x3[2]*w2 + x3[3]*w3;
                }
                float4 ov = make_float4(fmaxf(s.x, 0.f), fmaxf(s.y, 0.f),
                                        fmaxf(s.z, 0.f), fmaxf(s.w, 0.f));
                float* dst = nxt + (size_t)(n0 + rn) * Bb + rq * 4;
                asm volatile("st.global.cg.v4.f32 [%0], {%1,%2,%3,%4};"
                             :: "l"(dst), "f"(ov.x), "f"(ov.y), "f"(ov.z), "f"(ov.w));
            }

            __threadfence();
            grid_barrier(step++);
            p ^= 1;
        }

        // ---- readout: one (o, b) output per block, warp 0 ----
        if (w == 0) {
            const int o = blk >> 6;
            const int b = blk & 63;
            const float* hf = g_h[p];
            float a = 0.0f;
            #pragma unroll
            for (int jj = 0; jj < 4; ++jj) {
                int j = l + jj * 32;
                float hv;
                const float* hp = hf + (size_t)s_out_idx[j] * Bb + b;
                asm volatile("ld.global.cg.f32 %0, [%1];" : "=f"(hv) : "l"(hp));
                a += s_wout[o * NOUT + j] * hv;
            }
            #pragma unroll
            for (int off = 16; off > 0; off >>= 1)
                a += __shfl_xor_sync(0xFFFFFFFFu, a, off);
            if (l == 0)
                out[(size_t)b * (Tt * Oo) + t * Oo + o] = a + b_out[o];
        }
    }
}

extern "C" void kernel_launch(void* const* d_in, const int* in_sizes, int n_in,
                              void* d_out, int out_size) {
    (void)in_sizes; (void)n_in; (void)out_size;
    const float* inputs = (const float*)d_in[0];
    const float* W_rec  = (const float*)d_in[1];
    const float* W_in   = (const float*)d_in[2];
    const float* b_in   = (const float*)d_in[3];
    const float* W_out  = (const float*)d_in[4];
    const float* b_out  = (const float*)d_in[5];
    const void*  s_idx  = d_in[6];
    const void*  o_idx  = d_in[7];

    cudaFuncSetAttribute(hx_rnn_kernel,
                         cudaFuncAttributeMaxDynamicSharedMemorySize, SMEM_DYN);

    hx_init_kernel<<<128, 256>>>();
    hx_rnn_kernel<<<NBLK, NTHREADS, SMEM_DYN>>>(inputs, W_rec, W_in, b_in,
                                                W_out, b_out, s_idx, o_idx,
                                                (float*)d_out);
}

// round 4
// speedup vs baseline: 2.9624x; 1.0700x over previous
#include <cuda_runtime.h>
#include <cstdint>

#define Nn 2048
#define Bb 64
#define Tt 128
#define Ii 4
#define NSENS 256
#define NOUT 128
#define Oo 2
#define KMICRO 4
#define NBLK 128
#define NT 16              // neurons per block
#define NTHREADS 512
#define NWARP 16
#define KSL (Nn / NWARP)   // 128 k per warp (split-K 16)
#define SMEM_DYN (NWARP * NT * Bb * 4)   // 64KB split-K partials

// persistent state: h double buffer, layout [neuron][batch]
__device__ __align__(128) float g_h[2][Nn * Bb];
// W transposed per block tile: W_T[blk][k][16 n], 16MB scratch
__device__ __align__(128) float g_WT[Nn * Nn];
__device__ unsigned g_count;
__device__ volatile unsigned g_gen;

__global__ void hx_init_kernel() {
    int i = blockIdx.x * blockDim.x + threadIdx.x;
    if (i == 0) { g_count = 0u; g_gen = 0u; }
    int stride = gridDim.x * blockDim.x;
    for (int j = i; j < Nn * Bb; j += stride) {
        g_h[0][j] = 0.0f;
        g_h[1][j] = 0.0f;
    }
}

// one-time: W[n][k] row-major -> W_T[blk][k][16n] (64B-contiguous per k)
__global__ void __launch_bounds__(256) hx_transpose_kernel(const float* __restrict__ W) {
    __shared__ float st[256 * 17];   // padded to kill bank conflicts
    const int blk = blockIdx.x;
    const int tid = threadIdx.x;
    const int n0 = blk * NT;
    for (int kc = 0; kc < Nn; kc += 256) {
        #pragma unroll
        for (int n = 0; n < NT; ++n)
            st[tid * 17 + n] = W[(size_t)(n0 + n) * Nn + kc + tid];
        __syncthreads();
        float* dst = g_WT + ((size_t)blk * Nn + kc) * NT;
        #pragma unroll
        for (int j = tid; j < 256 * NT; j += 256)
            dst[j] = st[(j >> 4) * 17 + (j & 15)];
        __syncthreads();
    }
}

__device__ __forceinline__ void grid_barrier(unsigned step) {
    __syncthreads();
    if (threadIdx.x == 0) {
        unsigned a = atomicAdd(&g_count, 1u);
        if (a == (unsigned)(gridDim.x - 1)) {
            g_count = 0u;
            __threadfence();
            g_gen = step;
        } else {
            while (g_gen < step) { }
            __threadfence();
        }
    }
    __syncthreads();
}

#define FMA2(acc, hv, wf) do {                                        \
    unsigned long long _wp;                                           \
    asm("mov.b64 %0, {%1, %1};" : "=l"(_wp) : "f"(wf));               \
    asm("fma.rn.f32x2 %0, %1, %2, %3;"                                \
        : "=l"(acc) : "l"(hv), "l"(_wp), "l"(acc));                   \
} while (0)

__global__ void __launch_bounds__(NTHREADS, 1) hx_rnn_kernel(
    const float* __restrict__ inputs,   // [B, T, I]
    const float* __restrict__ W_in,     // [NSENS, I]
    const float* __restrict__ b_in,     // [NSENS]
    const float* __restrict__ W_out,    // [O, NOUT]
    const float* __restrict__ b_out,    // [O]
    const void*  sens_idx_p,
    const void*  out_idx_p,
    float* __restrict__ out)            // [B, T, O]
{
    extern __shared__ float spart[];    // [16 slice][16 n][64 b]

    __shared__ int s_map[NT];
    __shared__ int s_out_idx[NOUT];
    __shared__ float s_wout[Oo * NOUT];
    __shared__ int s_flags;

    const int tid = threadIdx.x;
    const int blk = blockIdx.x;
    const int n0 = blk * NT;

    // ---- index dtype detection (int64 vs int32) ----
    if (tid == 0) {
        const int* ws = (const int*)sens_idx_p;
        int s64 = 1;
        for (int i = 1; i < NSENS; i += 2) { if (ws[i] != 0) { s64 = 0; break; } }
        const int* wo = (const int*)out_idx_p;
        int o64 = 1;
        for (int i = 1; i < NOUT; i += 2) { if (wo[i] != 0) { o64 = 0; break; } }
        s_flags = s64 | (o64 << 1);
    }
    if (tid < NT) s_map[tid] = -1;
    __syncthreads();
    const bool s64 = (s_flags & 1) != 0;
    const bool o64 = (s_flags & 2) != 0;

    for (int s = tid; s < NSENS; s += NTHREADS) {
        int idx = s64 ? (int)((const long long*)sens_idx_p)[s]
                      : ((const int*)sens_idx_p)[s];
        if (idx >= n0 && idx < n0 + NT) s_map[idx - n0] = s;
    }
    for (int j = tid; j < NOUT; j += NTHREADS)
        s_out_idx[j] = o64 ? (int)((const long long*)out_idx_p)[j]
                           : ((const int*)out_idx_p)[j];
    for (int j = tid; j < Oo * NOUT; j += NTHREADS) s_wout[j] = W_out[j];
    __syncthreads();

    // ---- compute mapping: warp = k-slice; lane = 2 n-groups x 16 b-groups ----
    const int w  = tid >> 5;            // k-slice 0..15
    const int l  = tid & 31;
    const int ng = l >> 4;              // 0..1 -> neurons ng*8 .. +8
    const int bg = l & 15;              // batches bg*4 .. +4
    const int kbase = w * KSL;
    const float* wb = g_WT + ((size_t)blk * Nn + kbase) * NT + ng * 8;
    float* pp = spart + (w * NT + ng * 8) * Bb + bg * 4;

    // ---- reduction mapping: thread -> (n, batch-pair) ----
    const int rn = tid >> 5;            // 0..15 local neuron
    const int rp2 = tid & 31;           // b-pair 0..31
    const int r_slot = s_map[rn];
    const float* r_wi = (r_slot >= 0) ? (W_in + r_slot * Ii) : W_in;
    const float r_bi  = (r_slot >= 0) ? b_in[r_slot] : 0.0f;

    unsigned step = 1;
    int p = 0;

    for (int t = 0; t < Tt; ++t) {
        for (int mi = 0; mi < KMICRO; ++mi) {
            const float* cur = g_h[p];
            float* nxt = g_h[p ^ 1];

            unsigned long long acc[16];   // [8 n][2 b-pairs]
            #pragma unroll
            for (int i = 0; i < 16; ++i) acc[i] = 0ull;

            const float* hb = cur + (size_t)kbase * Bb + bg * 4;

            #pragma unroll 4
            for (int k = 0; k < KSL; ++k) {
                unsigned long long h01, h23;
                asm volatile("ld.global.cg.v2.u64 {%0,%1}, [%2];"
                             : "=l"(h01), "=l"(h23) : "l"(hb + k * Bb));
                const float4 wa = __ldg((const float4*)(wb + k * NT));
                const float4 wc = __ldg((const float4*)(wb + k * NT + 4));
                FMA2(acc[0],  h01, wa.x); FMA2(acc[1],  h23, wa.x);
                FMA2(acc[2],  h01, wa.y); FMA2(acc[3],  h23, wa.y);
                FMA2(acc[4],  h01, wa.z); FMA2(acc[5],  h23, wa.z);
                FMA2(acc[6],  h01, wa.w); FMA2(acc[7],  h23, wa.w);
                FMA2(acc[8],  h01, wc.x); FMA2(acc[9],  h23, wc.x);
                FMA2(acc[10], h01, wc.y); FMA2(acc[11], h23, wc.y);
                FMA2(acc[12], h01, wc.z); FMA2(acc[13], h23, wc.z);
                FMA2(acc[14], h01, wc.w); FMA2(acc[15], h23, wc.w);
            }

            // ---- write split-K partials (8 x STS.128) ----
            #pragma unroll
            for (int nn = 0; nn < 8; ++nn) {
                float f0, f1, f2, f3;
                asm("mov.b64 {%0,%1}, %2;" : "=f"(f0), "=f"(f1) : "l"(acc[nn * 2 + 0]));
                asm("mov.b64 {%0,%1}, %2;" : "=f"(f2), "=f"(f3) : "l"(acc[nn * 2 + 1]));
                *(float4*)(pp + nn * Bb) = make_float4(f0, f1, f2, f3);
            }
            __syncthreads();

            // ---- reduce 16 partials, inject, relu, store (1 b-pair/thread) ----
            {
                const float* rp = spart + rn * Bb + rp2 * 2;
                float s0 = 0.f, s1 = 0.f;
                #pragma unroll
                for (int ss = 0; ss < NWARP; ++ss) {
                    float2 q = *(const float2*)(rp + ss * NT * Bb);
                    s0 += q.x; s1 += q.y;
                }
                if (mi == 0 && r_slot >= 0) {
                    const float w0 = r_wi[0], w1 = r_wi[1], w2 = r_wi[2], w3 = r_wi[3];
                    const int b0 = rp2 * 2;
                    const float* x0 = inputs + (size_t)(b0 + 0) * (Tt * Ii) + t * Ii;
                    const float* x1 = inputs + (size_t)(b0 + 1) * (Tt * Ii) + t * Ii;
                    s0 += r_bi + x0[0]*w0 + x0[1]*w1 + x0[2]*w2 + x0[3]*w3;
                    s1 += r_bi + x1[0]*w0 + x1[1]*w1 + x1[2]*w2 + x1[3]*w3;
                }
                s0 = fmaxf(s0, 0.f);
                s1 = fmaxf(s1, 0.f);
                float* dst = nxt + (size_t)(n0 + rn) * Bb + rp2 * 2;
                asm volatile("st.global.cg.v2.f32 [%0], {%1,%2};"
                             :: "l"(dst), "f"(s0), "f"(s1));
            }

            __threadfence();
            grid_barrier(step++);
            p ^= 1;
        }

        // ---- readout: one (o, b) output per block, warp 0 ----
        if (w == 0) {
            const int o = blk >> 6;
            const int b = blk & 63;
            const float* hf = g_h[p];
            float a = 0.0f;
            #pragma unroll
            for (int jj = 0; jj < 4; ++jj) {
                int j = l + jj * 32;
                float hv;
                const float* hp = hf + (size_t)s_out_idx[j] * Bb + b;
                asm volatile("ld.global.cg.f32 %0, [%1];" : "=f"(hv) : "l"(hp));
                a += s_wout[o * NOUT + j] * hv;
            }
            #pragma unroll
            for (int off = 16; off > 0; off >>= 1)
                a += __shfl_xor_sync(0xFFFFFFFFu, a, off);
            if (l == 0)
                out[(size_t)b * (Tt * Oo) + t * Oo + o] = a + b_out[o];
        }
    }
}

extern "C" void kernel_launch(void* const* d_in, const int* in_sizes, int n_in,
                              void* d_out, int out_size) {
    (void)in_sizes; (void)n_in; (void)out_size;
    const float* inputs = (const float*)d_in[0];
    const float* W_rec  = (const float*)d_in[1];
    const float* W_in   = (const float*)d_in[2];
    const float* b_in   = (const float*)d_in[3];
    const float* W_out  = (const float*)d_in[4];
    const float* b_out  = (const float*)d_in[5];
    const void*  s_idx  = d_in[6];
    const void*  o_idx  = d_in[7];

    cudaFuncSetAttribute(hx_rnn_kernel,
                         cudaFuncAttributeMaxDynamicSharedMemorySize, SMEM_DYN);

    hx_init_kernel<<<128, 256>>>();
    hx_transpose_kernel<<<NBLK, 256>>>(W_rec);
    hx_rnn_kernel<<<NBLK, NTHREADS, SMEM_DYN>>>(inputs, W_in, b_in,
                                                W_out, b_out, s_idx, o_idx,
                                                (float*)d_out);
}

// round 6
// speedup vs baseline: 3.8477x; 1.2988x over previous
#include <cuda_runtime.h>
#include <cuda_bf16.h>
#include <cstdint>

#define Nn 2048
#define Bb 64
#define Tt 128
#define Ii 4
#define NSENS 256
#define NOUT 128
#define Oo 2
#define KMICRO 4
#define NBLK 128
#define NTHREADS 256
#define MTILE 128          // neurons per CTA MMA tile
#define KSLICE 256         // k per CTA (split-K 8)
#define NRED 16            // neurons per CTA in reduce phase
#define ROWB 528           // padded smem row stride (bytes) for 256 bf16

// dynamic smem layout (relative to 1024-aligned base)
#define OFF_AHI 0
#define OFF_ALO (MTILE * ROWB)                 // 67584
#define OFF_BHI (2 * MTILE * ROWB)             // 135168
#define OFF_BLO (2 * MTILE * ROWB + Bb * ROWB) // 168960
#define OFF_STHI (2 * MTILE * ROWB + 2 * Bb * ROWB)  // 202752
#define OFF_STLO (OFF_STHI + 2048)
#define SMEM_BYTES (OFF_STLO + 2048 + 1024)

// global state
__device__ __align__(128) float g_h[Nn * Bb];                 // fp32 [n][b]
__device__ __align__(128) __nv_bfloat16 g_hhi[Bb * Nn];       // [b][k]
__device__ __align__(128) __nv_bfloat16 g_hlo[Bb * Nn];       // [b][k]
__device__ __align__(128) float g_part[8][Nn * Bb];           // [ks][n][b]
__device__ unsigned g_count;
__device__ volatile unsigned g_gen;

__global__ void hx_init_kernel() {
    int i = blockIdx.x * blockDim.x + threadIdx.x;
    if (i == 0) { g_count = 0u; g_gen = 0u; }
    int stride = gridDim.x * blockDim.x;
    for (int j = i; j < Bb * Nn; j += stride) {
        g_hhi[j] = __float2bfloat16(0.0f);
        g_hlo[j] = __float2bfloat16(0.0f);
    }
}

__device__ __forceinline__ void grid_barrier(unsigned step) {
    __syncthreads();
    if (threadIdx.x == 0) {
        unsigned a = atomicAdd(&g_count, 1u);
        if (a == (unsigned)(gridDim.x - 1)) {
            g_count = 0u;
            __threadfence();
            g_gen = step;
        } else {
            while (g_gen < step) { }
            __threadfence();
        }
    }
    __syncthreads();
}

__device__ __forceinline__ uint32_t smem_u32(const void* p) {
    uint32_t a;
    asm("{ .reg .u64 t; cvta.to.shared.u64 t, %1; cvt.u32.u64 %0, t; }"
        : "=r"(a) : "l"(p));
    return a;
}

__device__ __forceinline__ void ldm4(uint32_t* r, uint32_t addr) {
    asm volatile("ldmatrix.sync.aligned.m8n8.x4.shared.b16 {%0,%1,%2,%3}, [%4];"
                 : "=r"(r[0]), "=r"(r[1]), "=r"(r[2]), "=r"(r[3]) : "r"(addr));
}

__device__ __forceinline__ void mma_bf16(float* c, const uint32_t* a,
                                         uint32_t b0, uint32_t b1) {
    asm volatile("mma.sync.aligned.m16n8k16.row.col.f32.bf16.bf16.f32 "
                 "{%0,%1,%2,%3}, {%4,%5,%6,%7}, {%8,%9}, {%0,%1,%2,%3};"
                 : "+f"(c[0]), "+f"(c[1]), "+f"(c[2]), "+f"(c[3])
                 : "r"(a[0]), "r"(a[1]), "r"(a[2]), "r"(a[3]),
                   "r"(b0), "r"(b1));
}

__global__ void __launch_bounds__(NTHREADS, 1) hx_rnn_kernel(
    const float* __restrict__ inputs,   // [B, T, I]
    const float* __restrict__ W,        // [N, N]
    const float* __restrict__ W_in,     // [NSENS, I]
    const float* __restrict__ b_in,     // [NSENS]
    const float* __restrict__ W_out,    // [O, NOUT]
    const float* __restrict__ b_out,    // [O]
    const void*  sens_idx_p,
    const void*  out_idx_p,
    float* __restrict__ out)            // [B, T, O]
{
    extern __shared__ char raw[];
    const uint32_t raw_u = smem_u32(raw);
    const uint32_t dyn_u = (raw_u + 1023u) & ~1023u;
    char* dyn = raw + (dyn_u - raw_u);

    __shared__ int s_map[NRED];
    __shared__ int s_out_idx[NOUT];
    __shared__ float s_wout[Oo * NOUT];
    __shared__ int s_flags;

    const int tid = threadIdx.x;
    const int blk = blockIdx.x;
    const int mt = blk >> 3;            // m-tile 0..15
    const int ks = blk & 7;             // k-slice 0..7
    const int n0 = blk * NRED;          // reduce ownership

    // ---- index dtype detection ----
    if (tid == 0) {
        const int* ws = (const int*)sens_idx_p;
        int s64 = 1;
        for (int i = 1; i < NSENS; i += 2) { if (ws[i] != 0) { s64 = 0; break; } }
        const int* wo = (const int*)out_idx_p;
        int o64 = 1;
        for (int i = 1; i < NOUT; i += 2) { if (wo[i] != 0) { o64 = 0; break; } }
        s_flags = s64 | (o64 << 1);
    }
    if (tid < NRED) s_map[tid] = -1;
    __syncthreads();
    const bool s64 = (s_flags & 1) != 0;
    const bool o64 = (s_flags & 2) != 0;

    for (int s = tid; s < NSENS; s += NTHREADS) {
        int idx = s64 ? (int)((const long long*)sens_idx_p)[s]
                      : ((const int*)sens_idx_p)[s];
        if (idx >= n0 && idx < n0 + NRED) s_map[idx - n0] = s;
    }
    for (int j = tid; j < NOUT; j += NTHREADS)
        s_out_idx[j] = o64 ? (int)((const long long*)out_idx_p)[j]
                           : ((const int*)out_idx_p)[j];
    for (int j = tid; j < Oo * NOUT; j += NTHREADS) s_wout[j] = W_out[j];

    // ---- one-time: W tile -> bf16 hi/lo, padded rows in smem ----
    for (int idx = tid; idx < MTILE * KSLICE; idx += NTHREADS) {
        int nl = idx >> 8;              // /256
        int k  = idx & 255;
        float w = __ldg(W + (size_t)(mt * MTILE + nl) * Nn + ks * KSLICE + k);
        __nv_bfloat16 hi = __float2bfloat16(w);
        __nv_bfloat16 lo = __float2bfloat16(w - __bfloat162float(hi));
        *(__nv_bfloat16*)(dyn + OFF_AHI + nl * ROWB + k * 2) = hi;
        *(__nv_bfloat16*)(dyn + OFF_ALO + nl * ROWB + k * 2) = lo;
    }
    __syncthreads();

    // ---- warp/lane mapping for MMA ----
    const int w  = tid >> 5;
    const int l  = tid & 31;
    const int warp_m = w & 3;           // 32-row group
    const int warp_n = w >> 2;          // 32-col group
    const uint32_t a_row = (uint32_t)((warp_m * 32 + (l & 15)) * ROWB + (l >> 4) * 16);
    const uint32_t b_row = (uint32_t)((warp_n * 32 + (l & 7) + ((l >> 4) << 3)) * ROWB
                                      + ((l >> 3) & 1) * 16);
    const uint32_t aHiAddr = dyn_u + OFF_AHI + a_row;
    const uint32_t aLoAddr = dyn_u + OFF_ALO + a_row;
    const uint32_t bHiAddr = dyn_u + OFF_BHI + b_row;
    const uint32_t bLoAddr = dyn_u + OFF_BLO + b_row;

    // reduce-phase constants
    const int rn = tid >> 4;            // 0..15 local neuron
    const int bq = tid & 15;            // batch quad
    const int r_slot = s_map[rn];
    const float* r_wi = (r_slot >= 0) ? (W_in + r_slot * Ii) : W_in;
    const float r_bi  = (r_slot >= 0) ? b_in[r_slot] : 0.0f;

    unsigned step = 1;

    for (int t = 0; t < Tt; ++t) {
        for (int mi = 0; mi < KMICRO; ++mi) {
            // ---- stage B tiles (h hi/lo) into padded smem ----
            #pragma unroll
            for (int hv = 0; hv < 2; ++hv) {
                const uint4* src = (const uint4*)(hv ? g_hlo : g_hhi);
                char* dstb = dyn + (hv ? OFF_BLO : OFF_BHI);
                #pragma unroll
                for (int i = 0; i < 8; ++i) {
                    int id = tid + i * NTHREADS;
                    int b = id >> 5, c16 = id & 31;
                    uint4 v = __ldcg(src + (((size_t)b * Nn + ks * KSLICE) >> 3) + c16);
                    *(uint4*)(dstb + b * ROWB + c16 * 16) = v;
                }
            }
            __syncthreads();

            // ---- MMA mainloop: acc = Whi*hhi + Whi*hlo + Wlo*hhi ----
            float acc[2][4][4];
            #pragma unroll
            for (int i = 0; i < 2; ++i)
                #pragma unroll
                for (int j = 0; j < 4; ++j)
                    #pragma unroll
                    for (int q = 0; q < 4; ++q) acc[i][j][q] = 0.0f;

            #pragma unroll 2
            for (int k = 0; k < 16; ++k) {
                const uint32_t ko = (uint32_t)k * 32u;
                uint32_t aHi[2][4], aLo[2][4], bHi[2][4], bLo[2][4];
                ldm4(aHi[0], aHiAddr + ko);
                ldm4(aHi[1], aHiAddr + 16 * ROWB + ko);
                ldm4(aLo[0], aLoAddr + ko);
                ldm4(aLo[1], aLoAddr + 16 * ROWB + ko);
                ldm4(bHi[0], bHiAddr + ko);
                ldm4(bHi[1], bHiAddr + 16 * ROWB + ko);
                ldm4(bLo[0], bLoAddr + ko);
                ldm4(bLo[1], bLoAddr + 16 * ROWB + ko);
                #pragma unroll
                for (int m2 = 0; m2 < 2; ++m2) {
                    #pragma unroll
                    for (int nt = 0; nt < 4; ++nt) {
                        const int g = nt >> 1, e = (nt & 1) * 2;
                        mma_bf16(acc[m2][nt], aHi[m2], bHi[g][e], bHi[g][e + 1]);
                        mma_bf16(acc[m2][nt], aHi[m2], bLo[g][e], bLo[g][e + 1]);
                        mma_bf16(acc[m2][nt], aLo[m2], bHi[g][e], bHi[g][e + 1]);
                    }
                }
            }

            // ---- epilogue: fragments -> g_part[ks] ----
            {
                float* base = g_part[ks] + (size_t)(mt * MTILE) * Bb;
                const int r_lo = warp_m * 32 + (l >> 2);
                const int c0 = warp_n * 32 + 2 * (l & 3);
                #pragma unroll
                for (int m2 = 0; m2 < 2; ++m2) {
                    #pragma unroll
                    for (int nt = 0; nt < 4; ++nt) {
                        const int rr = r_lo + m2 * 16;
                        const int cc = c0 + nt * 8;
                        asm volatile("st.global.cg.v2.f32 [%0], {%1,%2};"
                                     :: "l"(base + (size_t)rr * Bb + cc),
                                        "f"(acc[m2][nt][0]), "f"(acc[m2][nt][1]));
                        asm volatile("st.global.cg.v2.f32 [%0], {%1,%2};"
                                     :: "l"(base + (size_t)(rr + 8) * Bb + cc),
                                        "f"(acc[m2][nt][2]), "f"(acc[m2][nt][3]));
                    }
                }
            }
            __threadfence();
            grid_barrier(step++);

            // ---- reduce 8 K-slices, inject, relu, write h ----
            {
                const float* rp = g_part[0] + ((size_t)n0 + rn) * Bb + bq * 4;
                float4 s = make_float4(0.f, 0.f, 0.f, 0.f);
                #pragma unroll
                for (int kk = 0; kk < 8; ++kk) {
                    float4 q = __ldcg((const float4*)(rp + (size_t)kk * Nn * Bb));
                    s.x += q.x; s.y += q.y; s.z += q.z; s.w += q.w;
                }
                if (mi == 0 && r_slot >= 0) {
                    const float w0 = r_wi[0], w1 = r_wi[1], w2 = r_wi[2], w3 = r_wi[3];
                    const int b0 = bq * 4;
                    const float* x0 = inputs + (size_t)(b0 + 0) * (Tt * Ii) + t * Ii;
                    const float* x1 = inputs + (size_t)(b0 + 1) * (Tt * Ii) + t * Ii;
                    const float* x2 = inputs + (size_t)(b0 + 2) * (Tt * Ii) + t * Ii;
                    const float* x3 = inputs + (size_t)(b0 + 3) * (Tt * Ii) + t * Ii;
                    s.x += r_bi + x0[0]*w0 + x0[1]*w1 + x0[2]*w2 + x0[3]*w3;
                    s.y += r_bi + x1[0]*w0 + x1[1]*w1 + x1[2]*w2 + x1[3]*w3;
                    s.z += r_bi + x2[0]*w0 + x2[1]*w1 + x2[2]*w2 + x2[3]*w3;
                    s.w += r_bi + x3[0]*w0 + x3[1]*w1 + x3[2]*w2 + x3[3]*w3;
                }
                s.x = fmaxf(s.x, 0.f); s.y = fmaxf(s.y, 0.f);
                s.z = fmaxf(s.z, 0.f); s.w = fmaxf(s.w, 0.f);
                asm volatile("st.global.cg.v4.f32 [%0], {%1,%2,%3,%4};"
                             :: "l"(g_h + ((size_t)n0 + rn) * Bb + bq * 4),
                                "f"(s.x), "f"(s.y), "f"(s.z), "f"(s.w));

                __nv_bfloat16* sth = (__nv_bfloat16*)(dyn + OFF_STHI);
                __nv_bfloat16* stl = (__nv_bfloat16*)(dyn + OFF_STLO);
                #pragma unroll
                for (int j = 0; j < 4; ++j) {
                    float v = (j == 0) ? s.x : (j == 1) ? s.y : (j == 2) ? s.z : s.w;
                    __nv_bfloat16 hi = __float2bfloat16(v);
                    __nv_bfloat16 lo = __float2bfloat16(v - __bfloat162float(hi));
                    sth[(bq * 4 + j) * NRED + rn] = hi;
                    stl[(bq * 4 + j) * NRED + rn] = lo;
                }
            }
            __syncthreads();
            if (tid < 128) {           // coalesced copy of staged h rows
                int b = tid >> 1, half = tid & 1;
                uint4 vh = *(uint4*)(dyn + OFF_STHI + b * 32 + half * 16);
                uint4 vl = *(uint4*)(dyn + OFF_STLO + b * 32 + half * 16);
                asm volatile("st.global.cg.v4.b32 [%0], {%1,%2,%3,%4};"
                             :: "l"((char*)g_hhi + (size_t)b * Nn * 2 + blk * 32 + half * 16),
                                "r"(vh.x), "r"(vh.y), "r"(vh.z), "r"(vh.w));
                asm volatile("st.global.cg.v4.b32 [%0], {%1,%2,%3,%4};"
                             :: "l"((char*)g_hlo + (size_t)b * Nn * 2 + blk * 32 + half * 16),
                                "r"(vl.x), "r"(vl.y), "r"(vl.z), "r"(vl.w));
            }
            __threadfence();
            grid_barrier(step++);
        }

        // ---- readout: one (o, b) per block, warp 0 ----
        if (w == 0) {
            const int o = blk >> 6;
            const int b = blk & 63;
            float a = 0.0f;
            #pragma unroll
            for (int jj = 0; jj < 4; ++jj) {
                int j = l + jj * 32;
                float hv;
                const float* hp = g_h + (size_t)s_out_idx[j] * Bb + b;
                asm volatile("ld.global.cg.f32 %0, [%1];" : "=f"(hv) : "l"(hp));
                a += s_wout[o * NOUT + j] * hv;
            }
            #pragma unroll
            for (int off = 16; off > 0; off >>= 1)
                a += __shfl_xor_sync(0xFFFFFFFFu, a, off);
            if (l == 0)
                out[(size_t)b * (Tt * Oo) + t * Oo + o] = a + b_out[o];
        }
    }
}

extern "C" void kernel_launch(void* const* d_in, const int* in_sizes, int n_in,
                              void* d_out, int out_size) {
    (void)in_sizes; (void)n_in; (void)out_size;
    const float* inputs = (const float*)d_in[0];
    const float* W_rec  = (const float*)d_in[1];
    const float* W_in   = (const float*)d_in[2];
    const float* b_in   = (const float*)d_in[3];
    const float* W_out  = (const float*)d_in[4];
    const float* b_out  = (const float*)d_in[5];
    const void*  s_idx  = d_in[6];
    const void*  o_idx  = d_in[7];

    cudaFuncSetAttribute(hx_rnn_kernel,
                         cudaFuncAttributeMaxDynamicSharedMemorySize, SMEM_BYTES);

    hx_init_kernel<<<128, 256>>>();
    hx_rnn_kernel<<<NBLK, NTHREADS, SMEM_BYTES>>>(inputs, W_rec, W_in, b_in,
                                                  W_out, b_out, s_idx, o_idx,
                                                  (float*)d_out);
}

// round 7
// speedup vs baseline: 6.0915x; 1.5831x over previous
#include <cuda_runtime.h>
#include <cuda_bf16.h>
#include <cstdint>

#define Nn 2048
#define Bb 64
#define Tt 128
#define Ii 4
#define NSENS 256
#define NOUT 128
#define Oo 2
#define KMICRO 4
#define NBLK 128
#define NTHREADS 512
#define MTILE 128          // neurons per CTA MMA tile
#define KSLICE 256         // k per CTA (split-K 8)
#define ROWB 528           // padded smem row stride (bytes) for 256 bf16

// dynamic smem layout (relative to 1024-aligned base)
#define OFF_AHI 0
#define OFF_ALO (MTILE * ROWB)             // 67584
#define OFF_BHI (2 * MTILE * ROWB)         // 135168
#define OFF_BLO (OFF_BHI + Bb * ROWB)      // 168960
#define SMEM_BYTES (OFF_BLO + Bb * ROWB + 1024)   // 203776

// global state: triple-buffered raw accumulators acc[b][n] (pre-relu sums)
__device__ __align__(128) float g_acc[3][Bb * Nn];
__device__ unsigned g_count;
__device__ volatile unsigned g_gen;

__global__ void hx_init_kernel() {
    int i = blockIdx.x * blockDim.x + threadIdx.x;
    if (i == 0) { g_count = 0u; g_gen = 0u; }
    int stride = gridDim.x * blockDim.x;
    for (int j = i; j < 3 * Bb * Nn; j += stride)
        ((float*)g_acc)[j] = 0.0f;
}

__device__ __forceinline__ void grid_barrier(unsigned step) {
    __syncthreads();
    if (threadIdx.x == 0) {
        unsigned a = atomicAdd(&g_count, 1u);
        if (a == (unsigned)(gridDim.x - 1)) {
            g_count = 0u;
            __threadfence();
            g_gen = step;
        } else {
            while (g_gen < step) { }
            __threadfence();
        }
    }
    __syncthreads();
}

__device__ __forceinline__ uint32_t smem_u32(const void* p) {
    uint32_t a;
    asm("{ .reg .u64 t; cvta.to.shared.u64 t, %1; cvt.u32.u64 %0, t; }"
        : "=r"(a) : "l"(p));
    return a;
}

__device__ __forceinline__ void ldm4(uint32_t* r, uint32_t addr) {
    asm volatile("ldmatrix.sync.aligned.m8n8.x4.shared.b16 {%0,%1,%2,%3}, [%4];"
                 : "=r"(r[0]), "=r"(r[1]), "=r"(r[2]), "=r"(r[3]) : "r"(addr));
}

__device__ __forceinline__ void mma_bf16(float* c, const uint32_t* a,
                                         uint32_t b0, uint32_t b1) {
    asm volatile("mma.sync.aligned.m16n8k16.row.col.f32.bf16.bf16.f32 "
                 "{%0,%1,%2,%3}, {%4,%5,%6,%7}, {%8,%9}, {%0,%1,%2,%3};"
                 : "+f"(c[0]), "+f"(c[1]), "+f"(c[2]), "+f"(c[3])
                 : "r"(a[0]), "r"(a[1]), "r"(a[2]), "r"(a[3]),
                   "r"(b0), "r"(b1));
}

__device__ __forceinline__ void redg(float* p, float v) {
    asm volatile("red.global.add.f32 [%0], %1;" :: "l"(p), "f"(v) : "memory");
}

__global__ void __launch_bounds__(NTHREADS, 1) hx_rnn_kernel(
    const float* __restrict__ inputs,   // [B, T, I]
    const float* __restrict__ W,        // [N, N]
    const float* __restrict__ W_in,     // [NSENS, I]
    const float* __restrict__ b_in,     // [NSENS]
    const float* __restrict__ W_out,    // [O, NOUT]
    const float* __restrict__ b_out,    // [O]
    const void*  sens_idx_p,
    const void*  out_idx_p,
    float* __restrict__ out)            // [B, T, O]
{
    extern __shared__ char raw[];
    const uint32_t raw_u = smem_u32(raw);
    const uint32_t dyn_u = (raw_u + 1023u) & ~1023u;
    char* dyn = raw + (dyn_u - raw_u);

    __shared__ int s_kslot[KSLICE];     // local k -> sensory slot (or -1)
    __shared__ int s_out_idx[NOUT];
    __shared__ float s_wout[Oo * NOUT];
    __shared__ float4 s_win[NSENS];
    __shared__ float s_bin[NSENS];
    __shared__ int s_flags;

    const int tid = threadIdx.x;
    const int blk = blockIdx.x;
    const int mt = blk >> 3;            // m-tile 0..15
    const int ks = blk & 7;             // k-slice 0..7

    // ---- index dtype detection (int64 vs int32) ----
    if (tid == 0) {
        const int* ws = (const int*)sens_idx_p;
        int s64 = 1;
        for (int i = 1; i < NSENS; i += 2) { if (ws[i] != 0) { s64 = 0; break; } }
        const int* wo = (const int*)out_idx_p;
        int o64 = 1;
        for (int i = 1; i < NOUT; i += 2) { if (wo[i] != 0) { o64 = 0; break; } }
        s_flags = s64 | (o64 << 1);
    }
    for (int k = tid; k < KSLICE; k += NTHREADS) s_kslot[k] = -1;
    __syncthreads();
    const bool s64 = (s_flags & 1) != 0;
    const bool o64 = (s_flags & 2) != 0;

    for (int s = tid; s < NSENS; s += NTHREADS) {
        int idx = s64 ? (int)((const long long*)sens_idx_p)[s]
                      : ((const int*)sens_idx_p)[s];
        if (idx >= ks * KSLICE && idx < (ks + 1) * KSLICE)
            s_kslot[idx - ks * KSLICE] = s;
        s_win[s] = *(const float4*)(W_in + s * Ii);
        s_bin[s] = b_in[s];
    }
    for (int j = tid; j < NOUT; j += NTHREADS)
        s_out_idx[j] = o64 ? (int)((const long long*)out_idx_p)[j]
                           : ((const int*)out_idx_p)[j];
    for (int j = tid; j < Oo * NOUT; j += NTHREADS) s_wout[j] = W_out[j];

    // ---- one-time: W tile -> bf16 hi/lo, padded rows in smem ----
    for (int idx = tid; idx < MTILE * KSLICE; idx += NTHREADS) {
        int nl = idx >> 8;              // /256
        int k  = idx & 255;
        float w = __ldg(W + (size_t)(mt * MTILE + nl) * Nn + ks * KSLICE + k);
        __nv_bfloat16 hi = __float2bfloat16(w);
        __nv_bfloat16 lo = __float2bfloat16(w - __bfloat162float(hi));
        *(__nv_bfloat16*)(dyn + OFF_AHI + nl * ROWB + k * 2) = hi;
        *(__nv_bfloat16*)(dyn + OFF_ALO + nl * ROWB + k * 2) = lo;
    }
    __syncthreads();

    // ---- warp/lane mapping for MMA: 4x4 warp grid over 128m x 64n ----
    const int w  = tid >> 5;
    const int l  = tid & 31;
    const int warp_m = w & 3;           // 32-row group
    const int warp_n = w >> 2;          // 16-col group
    const uint32_t aHiAddr = dyn_u + OFF_AHI
        + (uint32_t)((warp_m * 32 + (l & 15)) * ROWB + (l >> 4) * 16);
    const uint32_t aLoAddr = aHiAddr + (OFF_ALO - OFF_AHI);
    const uint32_t bHiAddr = dyn_u + OFF_BHI
        + (uint32_t)((warp_n * 16 + (l & 7) + ((l >> 4) << 3)) * ROWB
                     + ((l >> 3) & 1) * 16);
    const uint32_t bLoAddr = bHiAddr + (OFF_BLO - OFF_BHI);

    // stage mapping: thread -> (batch, k-group)
    const int b_s = tid >> 3;           // 0..63
    const int kg  = tid & 7;

    // epilogue (REDG) coordinates
    const int n_eb = mt * MTILE + warp_m * 32 + (l >> 2);
    const int b_eb = warp_n * 16 + 2 * (l & 3);

    unsigned step = 1;

    for (int t = 0; t < Tt; ++t) {
        for (int mi = 0; mi < KMICRO; ++mi) {
            const int g = t * KMICRO + mi;
            const float* acc_prev = g_acc[(g + 2) % 3];
            float* acc_cur  = g_acc[g % 3];
            float* acc_zero = g_acc[(g + 1) % 3];

            // ---- stage: read raw sums, inject+relu, split bf16 hi/lo -> smem ----
            {
                const float* ap = acc_prev + (size_t)b_s * Nn + ks * KSLICE;
                float4 xv = make_float4(0.f, 0.f, 0.f, 0.f);
                if (mi == 0)
                    xv = *(const float4*)(inputs + (size_t)b_s * (Tt * Ii) + t * Ii);
                char* bhi = dyn + OFF_BHI + b_s * ROWB;
                char* blo = dyn + OFF_BLO + b_s * ROWB;
                #pragma unroll
                for (int i = 0; i < 8; ++i) {
                    const int k0 = kg * 4 + i * 32;
                    float4 q = __ldcg((const float4*)(ap + k0));
                    float vj[4] = {q.x, q.y, q.z, q.w};
                    if (mi == 0) {
                        #pragma unroll
                        for (int j = 0; j < 4; ++j) {
                            int s = s_kslot[k0 + j];
                            if (s >= 0) {
                                float4 wv = s_win[s];
                                vj[j] += s_bin[s] + wv.x * xv.x + wv.y * xv.y
                                       + wv.z * xv.z + wv.w * xv.w;
                            }
                        }
                    }
                    uint32_t uh[2], ul[2];
                    #pragma unroll
                    for (int j = 0; j < 2; ++j) {
                        float v0 = fmaxf(vj[2 * j], 0.f);
                        float v1 = fmaxf(vj[2 * j + 1], 0.f);
                        __nv_bfloat16 h0 = __float2bfloat16(v0);
                        __nv_bfloat16 h1 = __float2bfloat16(v1);
                        float l0 = v0 - __bfloat162float(h0);
                        float l1 = v1 - __bfloat162float(h1);
                        __nv_bfloat162 hh = __halves2bfloat162(h0, h1);
                        __nv_bfloat162 ll = __halves2bfloat162(
                            __float2bfloat16(l0), __float2bfloat16(l1));
                        uh[j] = *(uint32_t*)&hh;
                        ul[j] = *(uint32_t*)&ll;
                    }
                    *(uint2*)(bhi + k0 * 2) = make_uint2(uh[0], uh[1]);
                    *(uint2*)(blo + k0 * 2) = make_uint2(ul[0], ul[1]);
                }
                // zero the buffer that will be REDG'd next microstep
                *(float2*)(acc_zero + blk * (NTHREADS * 2) + tid * 2)
                    = make_float2(0.f, 0.f);
            }

            // ---- readout for timestep t (during last microstep) ----
            if (mi == KMICRO - 1 && w == 0) {
                const int o = blk >> 6;
                const int bb = blk & 63;
                const float* hr = acc_prev + (size_t)bb * Nn;
                float a = 0.0f;
                #pragma unroll
                for (int jj = 0; jj < 4; ++jj) {
                    int j = l + jj * 32;
                    float hv;
                    asm volatile("ld.global.cg.f32 %0, [%1];"
                                 : "=f"(hv) : "l"(hr + s_out_idx[j]));
                    a += s_wout[o * NOUT + j] * fmaxf(hv, 0.f);
                }
                #pragma unroll
                for (int off = 16; off > 0; off >>= 1)
                    a += __shfl_xor_sync(0xFFFFFFFFu, a, off);
                if (l == 0)
                    out[(size_t)bb * (Tt * Oo) + t * Oo + o] = a + b_out[o];
            }
            __syncthreads();

            // ---- MMA + REDG epilogue (skipped on final microstep) ----
            if (!(t == Tt - 1 && mi == KMICRO - 1)) {
                float facc[2][2][4];
                #pragma unroll
                for (int i = 0; i < 2; ++i)
                    #pragma unroll
                    for (int j = 0; j < 2; ++j)
                        #pragma unroll
                        for (int q = 0; q < 4; ++q) facc[i][j][q] = 0.0f;

                #pragma unroll 2
                for (int k = 0; k < 16; ++k) {
                    const uint32_t ko = (uint32_t)k * 32u;
                    uint32_t a0h[4], a1h[4], a0l[4], a1l[4], bh[4], bl[4];
                    ldm4(a0h, aHiAddr + ko);
                    ldm4(a1h, aHiAddr + 16 * ROWB + ko);
                    ldm4(a0l, aLoAddr + ko);
                    ldm4(a1l, aLoAddr + 16 * ROWB + ko);
                    ldm4(bh, bHiAddr + ko);
                    ldm4(bl, bLoAddr + ko);
                    #pragma unroll
                    for (int nf = 0; nf < 2; ++nf) {
                        mma_bf16(facc[0][nf], a0h, bh[2 * nf], bh[2 * nf + 1]);
                        mma_bf16(facc[1][nf], a1h, bh[2 * nf], bh[2 * nf + 1]);
                        mma_bf16(facc[0][nf], a0h, bl[2 * nf], bl[2 * nf + 1]);
                        mma_bf16(facc[1][nf], a1h, bl[2 * nf], bl[2 * nf + 1]);
                        mma_bf16(facc[0][nf], a0l, bh[2 * nf], bh[2 * nf + 1]);
                        mma_bf16(facc[1][nf], a1l, bh[2 * nf], bh[2 * nf + 1]);
                    }
                }

                #pragma unroll
                for (int m2 = 0; m2 < 2; ++m2) {
                    #pragma unroll
                    for (int nf = 0; nf < 2; ++nf) {
                        float* p0 = acc_cur + (size_t)(b_eb + nf * 8) * Nn
                                  + (n_eb + m2 * 16);
                        redg(p0,          facc[m2][nf][0]);
                        redg(p0 + Nn,     facc[m2][nf][1]);
                        redg(p0 + 8,      facc[m2][nf][2]);
                        redg(p0 + Nn + 8, facc[m2][nf][3]);
                    }
                }
            }

            __threadfence();
            grid_barrier(step++);
        }
    }
}

extern "C" void kernel_launch(void* const* d_in, const int* in_sizes, int n_in,
                              void* d_out, int out_size) {
    (void)in_sizes; (void)n_in; (void)out_size;
    const float* inputs = (const float*)d_in[0];
    const float* W_rec  = (const float*)d_in[1];
    const float* W_in   = (const float*)d_in[2];
    const float* b_in   = (const float*)d_in[3];
    const float* W_out  = (const float*)d_in[4];
    const float* b_out  = (const float*)d_in[5];
    const void*  s_idx  = d_in[6];
    const void*  o_idx  = d_in[7];

    cudaFuncSetAttribute(hx_rnn_kernel,
                         cudaFuncAttributeMaxDynamicSharedMemorySize, SMEM_BYTES);

    hx_init_kernel<<<128, 256>>>();
    hx_rnn_kernel<<<NBLK, NTHREADS, SMEM_BYTES>>>(inputs, W_rec, W_in, b_in,
                                                  W_out, b_out, s_idx, o_idx,
                                                  (float*)d_out);
}

// round 8
// speedup vs baseline: 6.6684x; 1.0947x over previous
#include <cuda_runtime.h>
#include <cuda_bf16.h>
#include <cstdint>

#define Nn 2048
#define Bb 64
#define Tt 128
#define Ii 4
#define NSENS 256
#define NOUT 128
#define Oo 2
#define KMICRO 4
#define NBLK 128
#define NTHREADS 512
#define MTILE 128          // neurons per CTA tile (N dim of MMA now)
#define KSLICE 256         // k per CTA (split-K 8)
#define ROWB 528           // padded smem row stride (bytes) for 256 bf16

// dynamic smem layout (relative to 1024-aligned base)
#define OFF_WHI 0
#define OFF_WLO (MTILE * ROWB)             // 67584
#define OFF_HHI (2 * MTILE * ROWB)         // 135168
#define OFF_HLO (OFF_HHI + Bb * ROWB)      // 168960
#define SMEM_BYTES (OFF_HLO + Bb * ROWB + 1024)   // 203776

// global state: triple-buffered raw accumulators acc[b][n] (pre-relu sums)
__device__ __align__(128) float g_acc[3][Bb * Nn];
__device__ unsigned g_count;
__device__ volatile unsigned g_gen;

__global__ void hx_init_kernel() {
    int i = blockIdx.x * blockDim.x + threadIdx.x;
    if (i == 0) { g_count = 0u; g_gen = 0u; }
    int stride = gridDim.x * blockDim.x;
    for (int j = i; j < 3 * Bb * Nn; j += stride)
        ((float*)g_acc)[j] = 0.0f;
}

__device__ __forceinline__ void grid_barrier(unsigned step) {
    __syncthreads();
    if (threadIdx.x == 0) {
        unsigned a = atomicAdd(&g_count, 1u);
        if (a == (unsigned)(gridDim.x - 1)) {
            g_count = 0u;
            __threadfence();
            g_gen = step;
        } else {
            while (g_gen < step) { }
            __threadfence();
        }
    }
    __syncthreads();
}

__device__ __forceinline__ uint32_t smem_u32(const void* p) {
    uint32_t a;
    asm("{ .reg .u64 t; cvta.to.shared.u64 t, %1; cvt.u32.u64 %0, t; }"
        : "=r"(a) : "l"(p));
    return a;
}

__device__ __forceinline__ void ldm4(uint32_t* r, uint32_t addr) {
    asm volatile("ldmatrix.sync.aligned.m8n8.x4.shared.b16 {%0,%1,%2,%3}, [%4];"
                 : "=r"(r[0]), "=r"(r[1]), "=r"(r[2]), "=r"(r[3]) : "r"(addr));
}

__device__ __forceinline__ void mma_bf16(float* c, const uint32_t* a,
                                         uint32_t b0, uint32_t b1) {
    asm volatile("mma.sync.aligned.m16n8k16.row.col.f32.bf16.bf16.f32 "
                 "{%0,%1,%2,%3}, {%4,%5,%6,%7}, {%8,%9}, {%0,%1,%2,%3};"
                 : "+f"(c[0]), "+f"(c[1]), "+f"(c[2]), "+f"(c[3])
                 : "r"(a[0]), "r"(a[1]), "r"(a[2]), "r"(a[3]),
                   "r"(b0), "r"(b1));
}

__device__ __forceinline__ void redg2(float* p, float v0, float v1) {
    asm volatile("red.global.add.v2.f32 [%0], {%1,%2};"
                 :: "l"(p), "f"(v0), "f"(v1) : "memory");
}

__global__ void __launch_bounds__(NTHREADS, 1) hx_rnn_kernel(
    const float* __restrict__ inputs,   // [B, T, I]
    const float* __restrict__ W,        // [N, N]
    const float* __restrict__ W_in,     // [NSENS, I]
    const float* __restrict__ b_in,     // [NSENS]
    const float* __restrict__ W_out,    // [O, NOUT]
    const float* __restrict__ b_out,    // [O]
    const void*  sens_idx_p,
    const void*  out_idx_p,
    float* __restrict__ out)            // [B, T, O]
{
    extern __shared__ char raw[];
    const uint32_t raw_u = smem_u32(raw);
    const uint32_t dyn_u = (raw_u + 1023u) & ~1023u;
    char* dyn = raw + (dyn_u - raw_u);

    __shared__ int s_kslot[KSLICE];     // local k -> sensory slot (or -1)
    __shared__ int s_out_idx[NOUT];
    __shared__ float s_wout[Oo * NOUT];
    __shared__ float4 s_win[NSENS];
    __shared__ float s_bin[NSENS];
    __shared__ int s_flags;

    const int tid = threadIdx.x;
    const int blk = blockIdx.x;
    const int mt = blk >> 3;            // n-tile (neurons) 0..15
    const int ks = blk & 7;             // k-slice 0..7

    // ---- index dtype detection (int64 vs int32) ----
    if (tid == 0) {
        const int* ws = (const int*)sens_idx_p;
        int s64 = 1;
        for (int i = 1; i < NSENS; i += 2) { if (ws[i] != 0) { s64 = 0; break; } }
        const int* wo = (const int*)out_idx_p;
        int o64 = 1;
        for (int i = 1; i < NOUT; i += 2) { if (wo[i] != 0) { o64 = 0; break; } }
        s_flags = s64 | (o64 << 1);
    }
    for (int k = tid; k < KSLICE; k += NTHREADS) s_kslot[k] = -1;
    __syncthreads();
    const bool s64 = (s_flags & 1) != 0;
    const bool o64 = (s_flags & 2) != 0;

    for (int s = tid; s < NSENS; s += NTHREADS) {
        int idx = s64 ? (int)((const long long*)sens_idx_p)[s]
                      : ((const int*)sens_idx_p)[s];
        if (idx >= ks * KSLICE && idx < (ks + 1) * KSLICE)
            s_kslot[idx - ks * KSLICE] = s;
        s_win[s] = *(const float4*)(W_in + s * Ii);
        s_bin[s] = b_in[s];
    }
    for (int j = tid; j < NOUT; j += NTHREADS)
        s_out_idx[j] = o64 ? (int)((const long long*)out_idx_p)[j]
                           : ((const int*)out_idx_p)[j];
    for (int j = tid; j < Oo * NOUT; j += NTHREADS) s_wout[j] = W_out[j];

    // ---- one-time: W tile -> bf16 hi/lo, padded rows in smem ----
    for (int idx = tid; idx < MTILE * KSLICE; idx += NTHREADS) {
        int nl = idx >> 8;              // /256
        int k  = idx & 255;
        float w = __ldg(W + (size_t)(mt * MTILE + nl) * Nn + ks * KSLICE + k);
        __nv_bfloat16 hi = __float2bfloat16(w);
        __nv_bfloat16 lo = __float2bfloat16(w - __bfloat162float(hi));
        *(__nv_bfloat16*)(dyn + OFF_WHI + nl * ROWB + k * 2) = hi;
        *(__nv_bfloat16*)(dyn + OFF_WLO + nl * ROWB + k * 2) = lo;
    }
    __syncthreads();

    // ---- warp/lane mapping: 2(m=batch) x 8(n=neuron) warp grid ----
    const int w  = tid >> 5;
    const int l  = tid & 31;
    const int warp_m = w >> 3;          // 0..1 -> 32 batch rows
    const int warp_n = w & 7;           // 0..7 -> 16 neuron cols
    // A operand = h tile [b][k] (ldmatrix m16k16 x4 pattern)
    const uint32_t hHiAddr = dyn_u + OFF_HHI
        + (uint32_t)((warp_m * 32 + (l & 15)) * ROWB + (l >> 4) * 16);
    const uint32_t hLoAddr = hHiAddr + (OFF_HLO - OFF_HHI);
    // B operand = W tile [n][k] (ldmatrix n16k16 x4 pattern)
    const uint32_t wHiAddr = dyn_u + OFF_WHI
        + (uint32_t)((warp_n * 16 + (l & 7) + ((l >> 4) << 3)) * ROWB
                     + ((l >> 3) & 1) * 16);
    const uint32_t wLoAddr = wHiAddr + (OFF_WLO - OFF_WHI);

    // stage mapping: thread -> (batch, k-group)
    const int b_s = tid >> 3;           // 0..63
    const int kg  = tid & 7;

    // epilogue (REDG) coordinates: acc[b][n]
    const int b_eb = warp_m * 32 + (l >> 2);
    const int n_eb = mt * MTILE + warp_n * 16 + 2 * (l & 3);

    unsigned step = 1;

    for (int t = 0; t < Tt; ++t) {
        for (int mi = 0; mi < KMICRO; ++mi) {
            const int g = t * KMICRO + mi;
            const float* acc_prev = g_acc[(g + 2) % 3];
            float* acc_cur  = g_acc[g % 3];
            float* acc_zero = g_acc[(g + 1) % 3];

            // ---- stage: read raw sums, inject+relu, split bf16 hi/lo -> smem ----
            {
                const float* ap = acc_prev + (size_t)b_s * Nn + ks * KSLICE;
                float4 qv[8];
                #pragma unroll
                for (int i = 0; i < 8; ++i)
                    qv[i] = __ldcg((const float4*)(ap + kg * 4 + i * 32));

                float4 xv = make_float4(0.f, 0.f, 0.f, 0.f);
                if (mi == 0)
                    xv = *(const float4*)(inputs + (size_t)b_s * (Tt * Ii) + t * Ii);
                char* bhi = dyn + OFF_HHI + b_s * ROWB;
                char* blo = dyn + OFF_HLO + b_s * ROWB;
                #pragma unroll
                for (int i = 0; i < 8; ++i) {
                    const int k0 = kg * 4 + i * 32;
                    float vj[4] = {qv[i].x, qv[i].y, qv[i].z, qv[i].w};
                    if (mi == 0) {
                        #pragma unroll
                        for (int j = 0; j < 4; ++j) {
                            int s = s_kslot[k0 + j];
                            if (s >= 0) {
                                float4 wv = s_win[s];
                                vj[j] += s_bin[s] + wv.x * xv.x + wv.y * xv.y
                                       + wv.z * xv.z + wv.w * xv.w;
                            }
                        }
                    }
                    uint32_t uh[2], ul[2];
                    #pragma unroll
                    for (int j = 0; j < 2; ++j) {
                        float v0 = fmaxf(vj[2 * j], 0.f);
                        float v1 = fmaxf(vj[2 * j + 1], 0.f);
                        __nv_bfloat16 h0 = __float2bfloat16(v0);
                        __nv_bfloat16 h1 = __float2bfloat16(v1);
                        float l0 = v0 - __bfloat162float(h0);
                        float l1 = v1 - __bfloat162float(h1);
                        __nv_bfloat162 hh = __halves2bfloat162(h0, h1);
                        __nv_bfloat162 ll = __halves2bfloat162(
                            __float2bfloat16(l0), __float2bfloat16(l1));
                        uh[j] = *(uint32_t*)&hh;
                        ul[j] = *(uint32_t*)&ll;
                    }
                    *(uint2*)(bhi + k0 * 2) = make_uint2(uh[0], uh[1]);
                    *(uint2*)(blo + k0 * 2) = make_uint2(ul[0], ul[1]);
                }
                // zero the buffer that will be REDG'd next microstep
                *(float2*)(acc_zero + blk * (NTHREADS * 2) + tid * 2)
                    = make_float2(0.f, 0.f);
            }

            // ---- readout for timestep t (during last microstep) ----
            if (mi == KMICRO - 1 && w == 0) {
                const int o = blk >> 6;
                const int bb = blk & 63;
                const float* hr = acc_prev + (size_t)bb * Nn;
                float a = 0.0f;
                #pragma unroll
                for (int jj = 0; jj < 4; ++jj) {
                    int j = l + jj * 32;
                    float hv;
                    asm volatile("ld.global.cg.f32 %0, [%1];"
                                 : "=f"(hv) : "l"(hr + s_out_idx[j]));
                    a += s_wout[o * NOUT + j] * fmaxf(hv, 0.f);
                }
                #pragma unroll
                for (int off = 16; off > 0; off >>= 1)
                    a += __shfl_xor_sync(0xFFFFFFFFu, a, off);
                if (l == 0)
                    out[(size_t)bb * (Tt * Oo) + t * Oo + o] = a + b_out[o];
            }
            __syncthreads();

            // ---- MMA + vectorized REDG epilogue (skipped on final microstep) ----
            if (!(t == Tt - 1 && mi == KMICRO - 1)) {
                float facc[2][2][4];
                #pragma unroll
                for (int i = 0; i < 2; ++i)
                    #pragma unroll
                    for (int j = 0; j < 2; ++j)
                        #pragma unroll
                        for (int q = 0; q < 4; ++q) facc[i][j][q] = 0.0f;

                #pragma unroll 2
                for (int k = 0; k < 16; ++k) {
                    const uint32_t ko = (uint32_t)k * 32u;
                    uint32_t ah0[4], ah1[4], al0[4], al1[4], bh[4], bl[4];
                    ldm4(ah0, hHiAddr + ko);
                    ldm4(ah1, hHiAddr + 16 * ROWB + ko);
                    ldm4(al0, hLoAddr + ko);
                    ldm4(al1, hLoAddr + 16 * ROWB + ko);
                    ldm4(bh, wHiAddr + ko);
                    ldm4(bl, wLoAddr + ko);
                    #pragma unroll
                    for (int nf = 0; nf < 2; ++nf) {
                        mma_bf16(facc[0][nf], ah0, bh[2 * nf], bh[2 * nf + 1]);
                        mma_bf16(facc[1][nf], ah1, bh[2 * nf], bh[2 * nf + 1]);
                        mma_bf16(facc[0][nf], al0, bh[2 * nf], bh[2 * nf + 1]);
                        mma_bf16(facc[1][nf], al1, bh[2 * nf], bh[2 * nf + 1]);
                        mma_bf16(facc[0][nf], ah0, bl[2 * nf], bl[2 * nf + 1]);
                        mma_bf16(facc[1][nf], ah1, bl[2 * nf], bl[2 * nf + 1]);
                    }
                }

                #pragma unroll
                for (int m2 = 0; m2 < 2; ++m2) {
                    #pragma unroll
                    for (int nf = 0; nf < 2; ++nf) {
                        float* p = acc_cur + (size_t)(b_eb + m2 * 16) * Nn
                                 + (n_eb + nf * 8);
                        redg2(p,           facc[m2][nf][0], facc[m2][nf][1]);
                        redg2(p + 8 * Nn,  facc[m2][nf][2], facc[m2][nf][3]);
                    }
                }
            }

            __threadfence();
            grid_barrier(step++);
        }
    }
}

extern "C" void kernel_launch(void* const* d_in, const int* in_sizes, int n_in,
                              void* d_out, int out_size) {
    (void)in_sizes; (void)n_in; (void)out_size;
    const float* inputs = (const float*)d_in[0];
    const float* W_rec  = (const float*)d_in[1];
    const float* W_in   = (const float*)d_in[2];
    const float* b_in   = (const float*)d_in[3];
    const float* W_out  = (const float*)d_in[4];
    const float* b_out  = (const float*)d_in[5];
    const void*  s_idx  = d_in[6];
    const void*  o_idx  = d_in[7];

    cudaFuncSetAttribute(hx_rnn_kernel,
                         cudaFuncAttributeMaxDynamicSharedMemorySize, SMEM_BYTES);

    hx_init_kernel<<<128, 256>>>();
    hx_rnn_kernel<<<NBLK, NTHREADS, SMEM_BYTES>>>(inputs, W_rec, W_in, b_in,
                                                  W_out, b_out, s_idx, o_idx,
                                                  (float*)d_out);
}